// round 9
// baseline (speedup 1.0000x reference)
#include <cuda_runtime.h>
#include <cstdint>

#define H 128
#define W 128
#define NS 8
#define TY 16
#define SROWS (TY + 8)   // 24
#define SCOLS 136        // 128 + 8 halo; even => 8B alignment of windows holds
#define ROWB  (SCOLS * 4)

// Bank swizzle at 8B granularity: conflict-free stride-16B LDS.64.
__device__ __forceinline__ int swz(int byteoff) {
    return byteoff ^ ((byteoff >> 4) & 8);
}
__device__ __forceinline__ float2 lds2(const float* arr, int byteoff) {
    return *(const float2*)((const char*)arr + swz(byteoff));
}
__device__ __forceinline__ void sts1(float* arr, int byteoff, float v) {
    *(float*)((char*)arr + swz(byteoff)) = v;
}

__global__ void __launch_bounds__(128)
shifted_conv_kernel(const float* __restrict__ tens,
                    const float* __restrict__ filters,
                    const int* __restrict__ shifts,
                    float* __restrict__ out)
{
    __shared__ __align__(128) float s_a[SROWS * SCOLS];   // x[c]   (swizzled)
    __shared__ __align__(128) float s_b[SROWS * SCOLS];   // x[c+1] (swizzled)
    __shared__ float s_f[NS * 25];
    __shared__ int   s_sh[NS * 2];

    const int n    = blockIdx.x;        // 0..255 (B*C)
    const int y0   = blockIdx.y * TY;   // 0..112 step 16
    const int tid  = threadIdx.x;
    const int lane = tid & 31;
    const int wrp  = tid >> 5;

    for (int i = tid; i < NS * 25; i += 128) s_f[i] = filters[i];
    if (tid < NS * 2) s_sh[tid] = shifts[tid];

    // Stage input strip once (4-halo, zero-padded), two copies offset by one
    // element so every 8-wide window has an 8B-aligned base in one copy.
    const float* inp = tens + (size_t)n * (H * W);
    for (int idx = tid; idx < SROWS * SCOLS; idx += 128) {
        int r  = idx / SCOLS;
        int c  = idx - r * SCOLS;
        int gy = y0 - 4 + r;
        int gx = c - 4;
        float v = 0.0f;
        if (gy >= 0 && gy < H && gx >= 0 && gx < W)
            v = inp[gy * W + gx];
        sts1(s_a, idx * 4, v);
        if (c > 0) sts1(s_b, (idx - 1) * 4, v);
    }
    for (int r = tid; r < SROWS; r += 128)
        sts1(s_b, (r * SCOLS + SCOLS - 1) * 4, 0.0f);
    __syncthreads();

    const int ybase = wrp * 4;          // 4 output rows per warp
    const int xo    = 4 * lane;         // 4 output cols per lane
    float* outw = out + (size_t)n * (NS * H * W)
                      + (size_t)(y0 + ybase) * W + xo;

    #pragma unroll 1
    for (int s = 0; s < NS; ++s) {
        const int sy = s_sh[2 * s + 0];
        const int sx = s_sh[2 * s + 1];

        float F[25];
        #pragma unroll
        for (int t = 0; t < 25; ++t) F[t] = s_f[s * 25 + t];

        const int rowbase = ybase + 4 - sy;     // [0, 16]
        const int col0    = xo + 4 - sx;        // window start, [0, 128]

        // w[t] = x_pad[col0 + t]; 8B-aligned base regardless of sx parity:
        //   sx even -> col0 even -> s_a @ col0
        //   sx odd  -> col0 odd  -> s_b @ col0-1   (s_b[i] = x[i+1])
        const float* arr = (sx & 1) ? s_b : s_a;
        const int   colA = (sx & 1) ? (col0 - 1) : col0;
        const int   bo0  = rowbase * ROWB + colA * 4;

        float acc[4][4];
        #pragma unroll
        for (int yy = 0; yy < 4; ++yy)
            #pragma unroll
            for (int d = 0; d < 4; ++d) acc[yy][d] = 0.f;

        #pragma unroll
        for (int k = 0; k < 8; ++k) {
            const int bo = bo0 + k * ROWB;
            float2 a0 = lds2(arr, bo + 0);
            float2 a1 = lds2(arr, bo + 8);
            float2 a2 = lds2(arr, bo + 16);
            float2 a3 = lds2(arr, bo + 24);
            float w[8] = {a0.x, a0.y, a1.x, a1.y, a2.x, a2.y, a3.x, a3.y};
            #pragma unroll
            for (int yy = 0; yy < 4; ++yy) {
                const int i = k - yy;           // compile-time after unroll
                if (i >= 0 && i < 5) {
                    #pragma unroll
                    for (int d = 0; d < 4; ++d) {
                        #pragma unroll
                        for (int j = 0; j < 5; ++j)
                            acc[yy][d] = fmaf(F[i * 5 + j], w[d + j], acc[yy][d]);
                    }
                }
            }
        }

        float* ops = outw + (size_t)s * (H * W);
        #pragma unroll
        for (int yy = 0; yy < 4; ++yy)
            *(float4*)(ops + yy * W) =
                make_float4(acc[yy][0], acc[yy][1], acc[yy][2], acc[yy][3]);
    }
}

extern "C" void kernel_launch(void* const* d_in, const int* in_sizes, int n_in,
                              void* d_out, int out_size)
{
    const float* tens    = (const float*)d_in[0];
    const float* filters = (const float*)d_in[1];
    const int*   shifts  = (const int*)d_in[2];
    float*       out     = (float*)d_out;

    dim3 grid(256, H / TY);   // 2048 blocks
    shifted_conv_kernel<<<grid, 128>>>(tens, filters, shifts, out);
}